// round 1
// baseline (speedup 1.0000x reference)
#include <cuda_runtime.h>
#include <cuda_bf16.h>
#include <stdint.h>

// Embedding_44994077393181
// out[b,t,:] = W_emb_tok[ argnz(X[b,t,:]) , : ] + X_emb_pos[t,:]
// X: (2,2048,32000) fp32 one-hot; W: (32000,1024) fp32; pos: (2048,1024) fp32
// One CTA per (b,t) row: chunked early-exit scan for the one-hot index,
// then fused gather + positional add.

#define VOCAB   32000
#define EMB_DIM 1024
#define CTX     2048
#define NROWS   4096          // BATCH * CTX
#define THREADS 256
#define CHUNK   4096          // floats scanned per pass (THREADS * 4 * 4)
#define NPASS   8             // ceil(32000 / 4096)

__global__ __launch_bounds__(THREADS)
void embed_onehot_kernel(const float* __restrict__ X,
                         const float* __restrict__ W,
                         const float* __restrict__ pos,
                         float* __restrict__ out)
{
    const int row = blockIdx.x;            // 0..4095  (b = row / CTX, t = row % CTX)
    const int t   = row & (CTX - 1);
    const int tid = threadIdx.x;

    const float* xrow = X + (size_t)row * VOCAB;

    __shared__ int s_idx;
    if (tid == 0) s_idx = -1;
    __syncthreads();

    // Chunked early-exit scan: 4096 floats per pass (each thread: 4x float4),
    // check the shared flag between passes. Expected ~58% of the row read.
    #pragma unroll 1
    for (int pass = 0; pass < NPASS; ++pass) {
        const int base = pass * CHUNK;
        int found = -1;
        #pragma unroll
        for (int j = 0; j < 4; ++j) {
            const int i = base + ((j * THREADS + tid) << 2);
            if (i < VOCAB) {
                const float4 v = *reinterpret_cast<const float4*>(xrow + i);
                if (v.x != 0.0f) found = i;
                if (v.y != 0.0f) found = i + 1;
                if (v.z != 0.0f) found = i + 2;
                if (v.w != 0.0f) found = i + 3;
            }
        }
        if (found >= 0) s_idx = found;     // exactly one nonzero per row -> no race
        __syncthreads();
        if (s_idx >= 0) break;
    }

    int idx = s_idx;
    if (idx < 0) idx = 0;                  // safety (unreachable for valid one-hot)

    // Fused gather + positional add: 1024 floats = 256 threads * float4.
    const float4 wv = reinterpret_cast<const float4*>(W   + (size_t)idx * EMB_DIM)[tid];
    const float4 pv = reinterpret_cast<const float4*>(pos + (size_t)t   * EMB_DIM)[tid];
    float4 o;
    o.x = wv.x + pv.x;
    o.y = wv.y + pv.y;
    o.z = wv.z + pv.z;
    o.w = wv.w + pv.w;
    reinterpret_cast<float4*>(out + (size_t)row * EMB_DIM)[tid] = o;
}

extern "C" void kernel_launch(void* const* d_in, const int* in_sizes, int n_in,
                              void* d_out, int out_size)
{
    const float* X   = (const float*)d_in[0];   // (2,2048,32000)
    const float* W   = (const float*)d_in[1];   // (32000,1024)
    const float* pos = (const float*)d_in[2];   // (2048,1024)
    float* out = (float*)d_out;                 // (2,2048,1024)

    embed_onehot_kernel<<<NROWS, THREADS>>>(X, W, pos, out);
}